// round 1
// baseline (speedup 1.0000x reference)
#include <cuda_runtime.h>

#define Bb 8
#define Hh 9
#define Ee 128
#define Ss 1025
#define HE 1152     // Hh*Ee
#define PSTR 1028   // score-row stride in smem floats

typedef unsigned long long ull;

// ---------------- scratch (no allocations allowed) ----------------
__device__ float g_q[Bb * Hh * Ss * Ee];   // 9,446,400 floats
__device__ float g_k[Bb * Hh * Ss * Ee];
__device__ float g_v[Bb * Hh * Ss * Ee];
__device__ float g_ho[Bb * Ss * HE];       // head outputs [b][s][h*E+f]

// ---------------- f32x2 helpers ----------------
__device__ __forceinline__ ull fdup(float v) {
    unsigned u = __float_as_uint(v);
    return ((ull)u << 32) | (ull)u;
}
__device__ __forceinline__ void ffma2(ull& d, ull a, ull b) {
    asm("fma.rn.f32x2 %0, %1, %2, %0;" : "+l"(d) : "l"(a), "l"(b));
}
__device__ __forceinline__ float f2lo(ull v) { return __uint_as_float((unsigned)v); }
__device__ __forceinline__ float f2hi(ull v) { return __uint_as_float((unsigned)(v >> 32)); }

// =================================================================
// Kernel 1: per-head projections  q/k/v[b,h,s,f] = sum_e x[b,e,s]*W[h,e,f]
// grid (17, 72, 3), block 256. smem: xsd dup[64][129] + ws[128][132]
// =================================================================
__global__ __launch_bounds__(256) void proj_kernel(
    const float* __restrict__ x, const float* __restrict__ Qw,
    const float* __restrict__ Kw, const float* __restrict__ Vw)
{
    extern __shared__ unsigned char sm1[];
    ull*   xsd = (ull*)sm1;                      // [64][129] duplicated pairs
    float* ws  = (float*)(sm1 + 64 * 129 * 8);   // [128][132]

    const int tid = threadIdx.x;
    const int s0  = blockIdx.x * 64;
    const int bh  = blockIdx.y;
    const int z   = blockIdx.z;
    const int h   = bh % Hh;
    const int b   = bh / Hh;

    const float* Wm  = (z == 0) ? Qw : (z == 1) ? Kw : Vw;
    float*       dst = (z == 0) ? g_q : (z == 1) ? g_k : g_v;

    // x tile, transposed to [s_local][e], zero-padded, duplicated
    #pragma unroll
    for (int it = 0; it < 32; ++it) {
        int idx = tid + it * 256;
        int e = idx >> 6, i = idx & 63;
        int s = s0 + i;
        float v = (s < Ss) ? x[((size_t)b * Ee + e) * Ss + s] : 0.f;
        xsd[i * 129 + e] = fdup(v);
    }
    // weights [e_in][f]
    const float* Wh = Wm + (size_t)h * Ee * Ee;
    #pragma unroll
    for (int it = 0; it < 64; ++it) {
        int idx = tid + it * 256;
        int kk = idx >> 7, f = idx & 127;
        ws[kk * 132 + f] = Wh[idx];
    }
    __syncthreads();

    const int rg = tid >> 4, cg = tid & 15;   // 4 rows x 8 cols per thread
    ull acc[4][4];
    #pragma unroll
    for (int j = 0; j < 4; ++j)
        #pragma unroll
        for (int c = 0; c < 4; ++c) acc[j][c] = 0ull;

    #pragma unroll 4
    for (int kk = 0; kk < 128; ++kk) {
        ulonglong2 w0 = *(const ulonglong2*)&ws[kk * 132 + cg * 8];
        ulonglong2 w1 = *(const ulonglong2*)&ws[kk * 132 + cg * 8 + 4];
        #pragma unroll
        for (int j = 0; j < 4; ++j) {
            ull a = xsd[(rg * 4 + j) * 129 + kk];
            ffma2(acc[j][0], a, w0.x);
            ffma2(acc[j][1], a, w0.y);
            ffma2(acc[j][2], a, w1.x);
            ffma2(acc[j][3], a, w1.y);
        }
    }

    #pragma unroll
    for (int j = 0; j < 4; ++j) {
        int s = s0 + rg * 4 + j;
        if (s < Ss) {
            float4 r0, r1;
            r0.x = f2lo(acc[j][0]); r0.y = f2hi(acc[j][0]);
            r0.z = f2lo(acc[j][1]); r0.w = f2hi(acc[j][1]);
            r1.x = f2lo(acc[j][2]); r1.y = f2hi(acc[j][2]);
            r1.z = f2lo(acc[j][3]); r1.w = f2hi(acc[j][3]);
            float* p = dst + ((size_t)bh * Ss + s) * Ee + cg * 8;
            *(float4*)p = r0;
            *(float4*)(p + 4) = r1;
        }
    }
}

// =================================================================
// Kernel 2: attention for one (b,h, 32-query tile)
// scores -> smem, softmax (writes atten), AV -> g_ho
// grid (33, 72), block 256.
// smem: ps[32][1028] f32 | qsd[32][129] dup | kv[128][132] f32  = 232,192 B
// =================================================================
__global__ __launch_bounds__(256) void attn_kernel(float* __restrict__ atten)
{
    extern __shared__ unsigned char sm2[];
    float* ps  = (float*)sm2;                                     // scores/probs
    ull*   qsd = (ull*)(sm2 + 32 * PSTR * 4);                     // dup q tile
    float* kv  = (float*)(sm2 + 32 * PSTR * 4 + 32 * 129 * 8);    // k^T / v chunk

    const int tid = threadIdx.x;
    const int bh  = blockIdx.y;
    const int b   = bh / Hh, h = bh % Hh;
    const int s0  = blockIdx.x * 32;

    const float* gq = g_q + (size_t)bh * Ss * Ee;
    const float* gk = g_k + (size_t)bh * Ss * Ee;
    const float* gv = g_v + (size_t)bh * Ss * Ee;

    // q tile (zero padded, duplicated)
    #pragma unroll
    for (int it = 0; it < 16; ++it) {
        int idx = tid + it * 256;
        int r = idx >> 7, e = idx & 127;
        int s = s0 + r;
        float v = (s < Ss) ? gq[(size_t)s * Ee + e] : 0.f;
        qsd[r * 129 + e] = fdup(v);
    }

    const int rg = tid >> 5;   // 8 groups of 4 query rows
    const int cl = tid & 31;   // 32 groups of 4 keys / 4 out-cols

    // ---------- scores: ps[r][t] = scale * q_r . k_t ----------
    for (int c0 = 0; c0 < Ss; c0 += 128) {
        __syncthreads();
        // k chunk transposed: kv[e][t_local]
        #pragma unroll
        for (int it = 0; it < 64; ++it) {
            int idx = tid + it * 256;
            int t = idx >> 7, e = idx & 127;
            float v = (c0 + t < Ss) ? gk[(size_t)(c0 + t) * Ee + e] : 0.f;
            kv[e * 132 + t] = v;
        }
        __syncthreads();

        ull acc[4][2] = {{0ull,0ull},{0ull,0ull},{0ull,0ull},{0ull,0ull}};
        #pragma unroll 4
        for (int e = 0; e < 128; ++e) {
            ulonglong2 bv = *(const ulonglong2*)&kv[e * 132 + cl * 4];
            #pragma unroll
            for (int j = 0; j < 4; ++j) {
                ull a = qsd[(rg * 4 + j) * 129 + e];
                ffma2(acc[j][0], a, bv.x);
                ffma2(acc[j][1], a, bv.y);
            }
        }
        int col = c0 + cl * 4;
        if (col + 4 <= PSTR) {   // clip padded tail (real cols < 1025 always kept)
            const float scl = 0.08838834764831845f;  // 1/sqrt(128)
            #pragma unroll
            for (int j = 0; j < 4; ++j) {
                float4 r;
                r.x = f2lo(acc[j][0]) * scl; r.y = f2hi(acc[j][0]) * scl;
                r.z = f2lo(acc[j][1]) * scl; r.w = f2hi(acc[j][1]) * scl;
                *(float4*)&ps[(rg * 4 + j) * PSTR + col] = r;
            }
        }
    }
    __syncthreads();

    // ---------- softmax per row (8 threads/row), write atten ----------
    {
        int r = tid >> 3, l8 = tid & 7;
        float* prow = ps + r * PSTR;
        float m = -3.0e38f;
        for (int c = l8; c < Ss; c += 8) m = fmaxf(m, prow[c]);
        m = fmaxf(m, __shfl_xor_sync(0xffffffffu, m, 1));
        m = fmaxf(m, __shfl_xor_sync(0xffffffffu, m, 2));
        m = fmaxf(m, __shfl_xor_sync(0xffffffffu, m, 4));
        float sum = 0.f;
        for (int c = l8; c < Ss; c += 8) {
            float p = __expf(prow[c] - m);
            prow[c] = p;
            sum += p;
        }
        sum += __shfl_xor_sync(0xffffffffu, sum, 1);
        sum += __shfl_xor_sync(0xffffffffu, sum, 2);
        sum += __shfl_xor_sync(0xffffffffu, sum, 4);
        float inv = 1.f / sum;
        int s = s0 + r;
        if (s < Ss) {
            float* arow = atten + ((size_t)bh * Ss + s) * Ss;
            for (int c = l8; c < Ss; c += 8) {
                float p = prow[c] * inv;
                prow[c] = p;
                arow[c] = p;
            }
        } else {
            for (int c = l8; c < Ss; c += 8) prow[c] *= inv;
        }
    }

    // ---------- AV: out[r][e] = sum_t P[r][t] * v[t][e] ----------
    ull acc[4][2] = {{0ull,0ull},{0ull,0ull},{0ull,0ull},{0ull,0ull}};
    for (int c0 = 0; c0 < Ss; c0 += 128) {
        __syncthreads();
        #pragma unroll
        for (int it = 0; it < 64; ++it) {
            int idx = tid + it * 256;
            int t = idx >> 7, e = idx & 127;
            float v = (c0 + t < Ss) ? gv[(size_t)(c0 + t) * Ee + e] : 0.f;
            kv[t * 132 + e] = v;
        }
        __syncthreads();
        int tmax = min(128, Ss - c0);
        for (int tt = 0; tt < tmax; ++tt) {
            ulonglong2 bv = *(const ulonglong2*)&kv[tt * 132 + cl * 4];
            #pragma unroll
            for (int j = 0; j < 4; ++j) {
                ull a = fdup(ps[(rg * 4 + j) * PSTR + c0 + tt]);
                ffma2(acc[j][0], a, bv.x);
                ffma2(acc[j][1], a, bv.y);
            }
        }
    }
    #pragma unroll
    for (int j = 0; j < 4; ++j) {
        int s = s0 + rg * 4 + j;
        if (s < Ss) {
            float4 r;
            r.x = f2lo(acc[j][0]); r.y = f2hi(acc[j][0]);
            r.z = f2lo(acc[j][1]); r.w = f2hi(acc[j][1]);
            *(float4*)&g_ho[((size_t)b * Ss + s) * HE + h * Ee + cl * 4] = r;
        }
    }
}

// =================================================================
// Kernel 3: out[b,e,s] = g_ho[b,s,:] . W[e,:] + bias[e]
// grid 129, block 256. static smem (<48KB)
// =================================================================
__global__ __launch_bounds__(256) void outproj_kernel(
    const float* __restrict__ Wm, const float* __restrict__ bias,
    float* __restrict__ out)
{
    __shared__ __align__(16) ull   Asd[64 * 33];
    __shared__ __align__(16) float Ws[32 * 132];

    const int tid  = threadIdx.x;
    const int row0 = blockIdx.x * 64;
    const int rg = tid >> 4, cg = tid & 15;

    ull acc[4][4];
    #pragma unroll
    for (int j = 0; j < 4; ++j)
        #pragma unroll
        for (int c = 0; c < 4; ++c) acc[j][c] = 0ull;

    for (int k0 = 0; k0 < HE; k0 += 32) {
        __syncthreads();
        #pragma unroll
        for (int it = 0; it < 8; ++it) {
            int idx = tid + it * 256;
            int i = idx >> 5, kk = idx & 31;
            int row = row0 + i;
            float v = (row < Bb * Ss) ? g_ho[(size_t)row * HE + k0 + kk] : 0.f;
            Asd[i * 33 + kk] = fdup(v);
        }
        #pragma unroll
        for (int it = 0; it < 16; ++it) {
            int idx = tid + it * 256;
            int e = idx >> 5, kk = idx & 31;
            Ws[kk * 132 + e] = Wm[(size_t)e * HE + k0 + kk];
        }
        __syncthreads();
        #pragma unroll 4
        for (int kk = 0; kk < 32; ++kk) {
            ulonglong2 w0 = *(const ulonglong2*)&Ws[kk * 132 + cg * 8];
            ulonglong2 w1 = *(const ulonglong2*)&Ws[kk * 132 + cg * 8 + 4];
            #pragma unroll
            for (int j = 0; j < 4; ++j) {
                ull a = Asd[(rg * 4 + j) * 33 + kk];
                ffma2(acc[j][0], a, w0.x);
                ffma2(acc[j][1], a, w0.y);
                ffma2(acc[j][2], a, w1.x);
                ffma2(acc[j][3], a, w1.y);
            }
        }
    }

    #pragma unroll
    for (int j = 0; j < 4; ++j) {
        int row = row0 + rg * 4 + j;
        if (row < Bb * Ss) {
            int b = row / Ss, s = row % Ss;
            float* obase = out + (size_t)b * Ee * Ss + s;
            #pragma unroll
            for (int c = 0; c < 4; ++c) {
                int e = cg * 8 + c * 2;
                obase[(size_t)e * Ss]       = f2lo(acc[j][c]) + bias[e];
                obase[(size_t)(e + 1) * Ss] = f2hi(acc[j][c]) + bias[e + 1];
            }
        }
    }
}

// =================================================================
extern "C" void kernel_launch(void* const* d_in, const int* in_sizes, int n_in,
                              void* d_out, int out_size)
{
    const float* x    = (const float*)d_in[0];
    const float* Qw   = (const float*)d_in[1];
    const float* Kw   = (const float*)d_in[2];
    const float* Vw   = (const float*)d_in[3];
    const float* Wm   = (const float*)d_in[4];
    const float* bias = (const float*)d_in[5];

    float* out   = (float*)d_out;                    // [B,E,S]
    float* atten = out + (size_t)Bb * Ee * Ss;       // [B,H,S,S]

    const int smem1 = 64 * 129 * 8 + 128 * 132 * 4;                   // 133,632
    const int smem2 = 32 * PSTR * 4 + 32 * 129 * 8 + 128 * 132 * 4;   // 232,192

    cudaFuncSetAttribute(proj_kernel, cudaFuncAttributeMaxDynamicSharedMemorySize, smem1);
    cudaFuncSetAttribute(attn_kernel, cudaFuncAttributeMaxDynamicSharedMemorySize, smem2);

    proj_kernel<<<dim3(17, Bb * Hh, 3), 256, smem1>>>(x, Qw, Kw, Vw);
    attn_kernel<<<dim3(33, Bb * Hh), 256, smem2>>>(atten);
    outproj_kernel<<<129, 256>>>(Wm, bias, out);
}